// round 15
// baseline (speedup 1.0000x reference)
#include <cuda_runtime.h>

// HybridQuanvolutionFraudNet: reference output = log_softmax(logits, axis=-1)
// with logits of shape [B, 1]. log_softmax over a size-1 axis is identically
// 0.0 (shifted = x - max = 0; logsumexp(0) = 0). All upstream computation
// (quanvolution 4-qubit statevector sim, tanh MLP, final linear) is dead.
// Output = zeros(out_size, float32). Verified rel_err = 0.0 bitwise
// (R1, R3, R4, R9, R10).
//
// Converged. Measurements:
//   R1:  grid=2x256          wall 4.576 µs, ncu 3.360 µs
//   R3:  memset node         wall 5.50 µs (kernel node is cheaper; reverted)
//   R4:  grid=1x512          wall 5.536 µs, ncu 3.392 µs
//   R9:  grid=1x128          wall 16.0 µs (contended), ncu 3.520 µs
//   R10: grid=2x256 (this)   wall 4.608 µs, ncu 3.328 µs  <- best kernel time
//   R11-R14: infra acquisition timeouts — resubmitting unchanged.
// Kernel time is a grid-invariant ~3.3-3.5 µs launch/drain envelope with all
// pipes and DRAM at 0.0% (actual store work ~50 ns). Wall time = floor +
// replay dispatch + machine-contention noise. No kernel-controllable variable
// remains; this configuration is final.

__global__ void zero_out(float4* __restrict__ out) {
    // grid=2, block=256: 512 threads x 16B = 8192 B = 2048 floats, exact fit.
    out[blockIdx.x * 256 + threadIdx.x] = make_float4(0.f, 0.f, 0.f, 0.f);
}

__global__ void zero_out_generic(float* __restrict__ out, int n) {
    int i = blockIdx.x * blockDim.x + threadIdx.x;
    if (i < n) out[i] = 0.f;
}

extern "C" void kernel_launch(void* const* d_in, const int* in_sizes, int n_in,
                              void* d_out, int out_size) {
    (void)d_in; (void)in_sizes; (void)n_in;
    if (out_size == 2048) {
        zero_out<<<2, 256>>>((float4*)d_out);
    } else {
        int block = 256;
        int grid = (out_size + block - 1) / block;
        zero_out_generic<<<grid, block>>>((float*)d_out, out_size);
    }
}